// round 5
// baseline (speedup 1.0000x reference)
#include <cuda_runtime.h>
#include <cuda_bf16.h>
#include <cstdint>

#define D_MODEL 1024
#define NHEADS  16
#define HD      64
#define BATCH   4
#define SEQ     2048
#define MTOT    (BATCH*SEQ)   // 8192

// ---- mma.sync GEMM tiling ----
#define TM 128
#define TN 128
#define BK 32
#define NCHUNK (D_MODEL/BK)   // 32
#define LROW 40               // padded row length (elements) -> 80 bytes
#define MAT_BYTES (128*LROW*2)            // 10240
#define OFF_AH 0
#define OFF_AL (MAT_BYTES)
#define OFF_BH (2*MAT_BYTES)
#define OFF_BL (3*MAT_BYTES)
#define STAGE_BYTES (4*MAT_BYTES)         // 40960
#define GEMM_DYN (2*STAGE_BYTES)          // 81920

// ---- scratch (no cudaMalloc allowed); 16B-aligned for cp.async / float4 ----
__device__ __align__(16) float g_q[MTOT*D_MODEL];                 // [m][D]
__device__ __align__(16) float g_k[MTOT*D_MODEL];
__device__ __align__(16) float g_v[MTOT*D_MODEL];
__device__ __align__(16) __nv_bfloat16 g_xh[MTOT*D_MODEL];        // X split
__device__ __align__(16) __nv_bfloat16 g_xl[MTOT*D_MODEL];
__device__ __align__(16) __nv_bfloat16 g_wh[4*D_MODEL*D_MODEL];   // W^T split
__device__ __align__(16) __nv_bfloat16 g_wl[4*D_MODEL*D_MODEL];
__device__ __align__(16) __nv_bfloat16 g_ch[MTOT*D_MODEL];        // ctx split
__device__ __align__(16) __nv_bfloat16 g_cl[MTOT*D_MODEL];

// ===========================================================================
// PTX helpers (baseline PTX only — no sm_103a-gated instructions)
// ===========================================================================
__device__ __forceinline__ uint32_t smem_u32(const void* p) {
    uint32_t a;
    asm("{ .reg .u64 t; cvta.to.shared.u64 t, %1; cvt.u32.u64 %0, t; }"
        : "=r"(a) : "l"(p));
    return a;
}
__device__ __forceinline__ void cp16(uint32_t dst, const void* src) {
    asm volatile("cp.async.cg.shared.global [%0], [%1], 16;"
                 :: "r"(dst), "l"(src) : "memory");
}
__device__ __forceinline__ void ldsm4(uint32_t* r, uint32_t addr) {
    asm volatile("ldmatrix.sync.aligned.m8n8.x4.shared.b16 {%0,%1,%2,%3}, [%4];"
                 : "=r"(r[0]), "=r"(r[1]), "=r"(r[2]), "=r"(r[3]) : "r"(addr));
}
__device__ __forceinline__ void ldsm2(uint32_t* r, uint32_t addr) {
    asm volatile("ldmatrix.sync.aligned.m8n8.x2.shared.b16 {%0,%1}, [%2];"
                 : "=r"(r[0]), "=r"(r[1]) : "r"(addr));
}
__device__ __forceinline__ void mma16816(float* c, const uint32_t* a, const uint32_t* b) {
    asm volatile(
        "mma.sync.aligned.m16n8k16.row.col.f32.bf16.bf16.f32 "
        "{%0,%1,%2,%3}, {%4,%5,%6,%7}, {%8,%9}, {%0,%1,%2,%3};"
        : "+f"(c[0]), "+f"(c[1]), "+f"(c[2]), "+f"(c[3])
        : "r"(a[0]), "r"(a[1]), "r"(a[2]), "r"(a[3]), "r"(b[0]), "r"(b[1]));
}

// ===========================================================================
// Convert kernels
// ===========================================================================
__global__ __launch_bounds__(256) void cvt_x_kernel(const float* __restrict__ X)
{
    size_t i = ((size_t)blockIdx.x * 256 + threadIdx.x) * 4;
    float4 v = *(const float4*)(X + i);
    __nv_bfloat16 h0 = __float2bfloat16(v.x), h1 = __float2bfloat16(v.y);
    __nv_bfloat16 h2 = __float2bfloat16(v.z), h3 = __float2bfloat16(v.w);
    __nv_bfloat16 l0 = __float2bfloat16(v.x - __bfloat162float(h0));
    __nv_bfloat16 l1 = __float2bfloat16(v.y - __bfloat162float(h1));
    __nv_bfloat16 l2 = __float2bfloat16(v.z - __bfloat162float(h2));
    __nv_bfloat16 l3 = __float2bfloat16(v.w - __bfloat162float(h3));
    __nv_bfloat162 a, b, c, d;
    a.x = h0; a.y = h1;  b.x = h2; b.y = h3;
    c.x = l0; c.y = l1;  d.x = l2; d.y = l3;
    *(__nv_bfloat162*)(g_xh + i)     = a;
    *(__nv_bfloat162*)(g_xh + i + 2) = b;
    *(__nv_bfloat162*)(g_xl + i)     = c;
    *(__nv_bfloat162*)(g_xl + i + 2) = d;
}

// transpose + split: Wt[n][k] = W[k][n]
__global__ __launch_bounds__(256) void cvt_w_kernel(
    const float* __restrict__ Wq, const float* __restrict__ Wk,
    const float* __restrict__ Wv, const float* __restrict__ Wo)
{
    __shared__ float t[32][33];
    const float* W = (blockIdx.z == 0) ? Wq : (blockIdx.z == 1) ? Wk
                   : (blockIdx.z == 2) ? Wv : Wo;
    int n0 = blockIdx.x * 32, k0 = blockIdx.y * 32;
    int c = threadIdx.x & 31, r8 = threadIdx.x >> 5;
    #pragma unroll
    for (int it = 0; it < 4; it++)
        t[r8 + it * 8][c] = W[(size_t)(k0 + r8 + it * 8) * D_MODEL + n0 + c];
    __syncthreads();
    __nv_bfloat16* oh = g_wh + (size_t)blockIdx.z * D_MODEL * D_MODEL;
    __nv_bfloat16* ol = g_wl + (size_t)blockIdx.z * D_MODEL * D_MODEL;
    #pragma unroll
    for (int it = 0; it < 4; it++) {
        int n = n0 + r8 + it * 8;
        float v = t[c][r8 + it * 8];
        __nv_bfloat16 h = __float2bfloat16(v);
        __nv_bfloat16 l = __float2bfloat16(v - __bfloat162float(h));
        oh[(size_t)n * D_MODEL + k0 + c] = h;
        ol[(size_t)n * D_MODEL + k0 + c] = l;
    }
}

// ===========================================================================
// bf16 mma.sync GEMM with hi/lo split: C = (Ah+Al)(Bh+Bl)^T, fp32 accum.
// A [M][K] row-major bf16, B = W^T [N][K] row-major bf16 (= col-major [K][N]).
// 256 threads = 8 warps in 2(m) x 4(n); each warp 64x32 via 4x4 m16n8 frags.
// ===========================================================================
__device__ __forceinline__ void stage_tile(uint32_t sbase,
                                           const __nv_bfloat16* __restrict__ G,
                                           int r0, int k0, int tid)
{
    int row = tid >> 1;          // 0..127
    int cb  = (tid & 1) * 2;     // 16B-chunk base: 0 or 2
    const __nv_bfloat16* gp = G + (size_t)(r0 + row) * D_MODEL + k0 + cb * 8;
    uint32_t so = sbase + (uint32_t)row * (LROW * 2) + (uint32_t)cb * 16;
    cp16(so,      gp);
    cp16(so + 16, gp + 8);
}

__device__ __forceinline__ void gemm_mma(
    const __nv_bfloat16* __restrict__ Ah, const __nv_bfloat16* __restrict__ Al,
    const __nv_bfloat16* __restrict__ Bh, const __nv_bfloat16* __restrict__ Bl,
    float* __restrict__ Out, const float* __restrict__ bias,
    int m0, int n0)
{
    extern __shared__ __align__(16) char dyn[];
    const int tid = threadIdx.x;
    const int wid = tid >> 5, lane = tid & 31;
    const int wm = wid >> 2, wn = wid & 3;        // 2 x 4 warp grid
    const uint32_t sb = smem_u32(dyn);

    // per-lane ldmatrix byte offsets (within a matrix buffer)
    const uint32_t a_off = (uint32_t)(wm * 64 + (lane & 15)) * (LROW * 2)
                         + (uint32_t)(lane >> 4) * 16;
    const uint32_t b_off = (uint32_t)(wn * 32 + (lane & 7)) * (LROW * 2)
                         + (uint32_t)((lane >> 3) & 1) * 16;

    float acc[4][4][4];
    #pragma unroll
    for (int mt = 0; mt < 4; mt++)
        #pragma unroll
        for (int nt = 0; nt < 4; nt++)
            #pragma unroll
            for (int r = 0; r < 4; r++) acc[mt][nt][r] = 0.f;

    // prologue
    stage_tile(sb + OFF_AH, Ah, m0, 0, tid);
    stage_tile(sb + OFF_AL, Al, m0, 0, tid);
    stage_tile(sb + OFF_BH, Bh, n0, 0, tid);
    stage_tile(sb + OFF_BL, Bl, n0, 0, tid);
    asm volatile("cp.async.commit_group;" ::: "memory");

    for (int i = 0; i < NCHUNK; i++) {
        const uint32_t cur = sb + (uint32_t)(i & 1) * STAGE_BYTES;
        if (i + 1 < NCHUNK) {
            const uint32_t nxt = sb + (uint32_t)((i + 1) & 1) * STAGE_BYTES;
            const int k0 = (i + 1) * BK;
            stage_tile(nxt + OFF_AH, Ah, m0, k0, tid);
            stage_tile(nxt + OFF_AL, Al, m0, k0, tid);
            stage_tile(nxt + OFF_BH, Bh, n0, k0, tid);
            stage_tile(nxt + OFF_BL, Bl, n0, k0, tid);
            asm volatile("cp.async.commit_group;" ::: "memory");
            asm volatile("cp.async.wait_group 1;" ::: "memory");
        } else {
            asm volatile("cp.async.wait_group 0;" ::: "memory");
        }
        __syncthreads();

        #pragma unroll
        for (int kk = 0; kk < 2; kk++) {            // two k16 steps per BK=32
            const uint32_t ko = (uint32_t)kk * 32;  // 16 els * 2B
            uint32_t afh[4][4], afl[4][4], bfh[4][2], bfl[4][2];
            #pragma unroll
            for (int mt = 0; mt < 4; mt++) {
                ldsm4(afh[mt], cur + OFF_AH + a_off + (uint32_t)mt * 16 * (LROW * 2) + ko);
                ldsm4(afl[mt], cur + OFF_AL + a_off + (uint32_t)mt * 16 * (LROW * 2) + ko);
            }
            #pragma unroll
            for (int nt = 0; nt < 4; nt++) {
                ldsm2(bfh[nt], cur + OFF_BH + b_off + (uint32_t)nt * 8 * (LROW * 2) + ko);
                ldsm2(bfl[nt], cur + OFF_BL + b_off + (uint32_t)nt * 8 * (LROW * 2) + ko);
            }
            #pragma unroll
            for (int mt = 0; mt < 4; mt++)
                #pragma unroll
                for (int nt = 0; nt < 4; nt++) {
                    mma16816(acc[mt][nt], afh[mt], bfh[nt]);
                    mma16816(acc[mt][nt], afh[mt], bfl[nt]);
                    mma16816(acc[mt][nt], afl[mt], bfh[nt]);
                }
        }
        __syncthreads();
    }

    // epilogue: c0,c1 -> (row = lane>>2, cols (lane&3)*2 +{0,1}); c2,c3 -> row+8
    const int er = lane >> 2, ec = (lane & 3) * 2;
    #pragma unroll
    for (int mt = 0; mt < 4; mt++) {
        const int mrow = m0 + wm * 64 + mt * 16 + er;
        #pragma unroll
        for (int nt = 0; nt < 4; nt++) {
            const int ncol = n0 + wn * 32 + nt * 8 + ec;
            float2 lo, hi;
            lo.x = acc[mt][nt][0]; lo.y = acc[mt][nt][1];
            hi.x = acc[mt][nt][2]; hi.y = acc[mt][nt][3];
            if (bias) {
                lo.x += bias[ncol]; lo.y += bias[ncol + 1];
                hi.x += bias[ncol]; hi.y += bias[ncol + 1];
            }
            *(float2*)(Out + (size_t)mrow * D_MODEL + ncol)       = lo;
            *(float2*)(Out + (size_t)(mrow + 8) * D_MODEL + ncol) = hi;
        }
    }
}

__global__ __launch_bounds__(256, 1) void qkv_mma_kernel()
{
    const int z  = blockIdx.z;
    const int m0 = blockIdx.y * TM, n0 = blockIdx.x * TN;
    const __nv_bfloat16* Bh = g_wh + (size_t)z * D_MODEL * D_MODEL;
    const __nv_bfloat16* Bl = g_wl + (size_t)z * D_MODEL * D_MODEL;
    float* Out = (z == 0) ? g_q : (z == 1) ? g_k : g_v;
    gemm_mma(g_xh, g_xl, Bh, Bl, Out, nullptr, m0, n0);
}

__global__ __launch_bounds__(256, 1) void out_mma_kernel(
    const float* __restrict__ bo, float* __restrict__ out)
{
    const int m0 = blockIdx.y * TM, n0 = blockIdx.x * TN;
    const __nv_bfloat16* Bh = g_wh + (size_t)3 * D_MODEL * D_MODEL;
    const __nv_bfloat16* Bl = g_wl + (size_t)3 * D_MODEL * D_MODEL;
    gemm_mma(g_ch, g_cl, Bh, Bl, out, bo, m0, n0);
}

// ===========================================================================
// Flash attention, fp32, causal. q/k/v in [m][D] row-major; ctx written as
// bf16 hi/lo for the mma out-projection.
// ===========================================================================
#define ATTN_SMEM (4 * 64 * 68 * 4)

__global__ __launch_bounds__(256) void attn_kernel()
{
    extern __shared__ float sm[];
    float* sQt = sm;                // [64][68]  d-major Q (pre-scaled)
    float* sKt = sm + 64 * 68;      // [64][68]  d-major K
    float* sV  = sm + 2 * 64 * 68;  // [64][68]  k-major V
    float* sP  = sm + 3 * 64 * 68;  // [64][68]  row-major P

    const int tid = threadIdx.x;
    const int tx  = tid & 15, ty = tid >> 4;
    const int bh  = blockIdx.y;     // b*16 + h
    const int qt  = blockIdx.x;
    const int q0  = qt * 64;
    const int b   = bh >> 4, h = bh & 15;

    const float* Qg = g_q + (size_t)b * SEQ * D_MODEL + h * HD;
    const float* Kg = g_k + (size_t)b * SEQ * D_MODEL + h * HD;
    const float* Vg = g_v + (size_t)b * SEQ * D_MODEL + h * HD;

    {
        const int row = tid >> 2;
        const int dg  = (tid & 3) * 16;
        const float* src = Qg + (size_t)(q0 + row) * D_MODEL + dg;
        #pragma unroll
        for (int v = 0; v < 4; v++) {
            float4 t = *(const float4*)(src + v * 4);
            sQt[(dg + v * 4 + 0) * 68 + row] = t.x * 0.125f;
            sQt[(dg + v * 4 + 1) * 68 + row] = t.y * 0.125f;
            sQt[(dg + v * 4 + 2) * 68 + row] = t.z * 0.125f;
            sQt[(dg + v * 4 + 3) * 68 + row] = t.w * 0.125f;
        }
    }

    float accO[4][4];
    float m_run[4], l_run[4];
    #pragma unroll
    for (int i = 0; i < 4; i++) {
        m_run[i] = -1e30f;
        l_run[i] = 0.f;
        #pragma unroll
        for (int j = 0; j < 4; j++) accO[i][j] = 0.f;
    }

    for (int t = 0; t <= qt; t++) {
        const int k0 = t * 64;
        __syncthreads();

        {
            const int row = tid >> 2;
            const int dg  = (tid & 3) * 16;
            const float* ks = Kg + (size_t)(k0 + row) * D_MODEL + dg;
            const float* vs = Vg + (size_t)(k0 + row) * D_MODEL + dg;
            #pragma unroll
            for (int v = 0; v < 4; v++) {
                float4 tk = *(const float4*)(ks + v * 4);
                sKt[(dg + v * 4 + 0) * 68 + row] = tk.x;
                sKt[(dg + v * 4 + 1) * 68 + row] = tk.y;
                sKt[(dg + v * 4 + 2) * 68 + row] = tk.z;
                sKt[(dg + v * 4 + 3) * 68 + row] = tk.w;
                *(float4*)&sV[row * 68 + dg + v * 4] = *(const float4*)(vs + v * 4);
            }
        }
        __syncthreads();

        float sc[4][4];
        #pragma unroll
        for (int i = 0; i < 4; i++)
            #pragma unroll
            for (int j = 0; j < 4; j++) sc[i][j] = 0.f;

        #pragma unroll 16
        for (int d = 0; d < 64; d++) {
            float a[4], bb[4];
            *(float4*)a  = *(const float4*)&sQt[d * 68 + ty * 4];
            *(float4*)bb = *(const float4*)&sKt[d * 68 + tx * 4];
            #pragma unroll
            for (int i = 0; i < 4; i++)
                #pragma unroll
                for (int j = 0; j < 4; j++)
                    sc[i][j] = fmaf(a[i], bb[j], sc[i][j]);
        }

        if (t == qt) {
            #pragma unroll
            for (int i = 0; i < 4; i++)
                #pragma unroll
                for (int j = 0; j < 4; j++)
                    if (tx * 4 + j > ty * 4 + i) sc[i][j] = -1e30f;
        }

        #pragma unroll
        for (int i = 0; i < 4; i++) {
            float tm = fmaxf(fmaxf(sc[i][0], sc[i][1]), fmaxf(sc[i][2], sc[i][3]));
            tm = fmaxf(tm, __shfl_xor_sync(0xffffffffu, tm, 1, 16));
            tm = fmaxf(tm, __shfl_xor_sync(0xffffffffu, tm, 2, 16));
            tm = fmaxf(tm, __shfl_xor_sync(0xffffffffu, tm, 4, 16));
            tm = fmaxf(tm, __shfl_xor_sync(0xffffffffu, tm, 8, 16));

            float mnew   = fmaxf(m_run[i], tm);
            float sc_old = __expf(m_run[i] - mnew);
            m_run[i] = mnew;

            float tsum = 0.f;
            #pragma unroll
            for (int j = 0; j < 4; j++) {
                float p = __expf(sc[i][j] - mnew);
                sc[i][j] = p;
                tsum += p;
            }
            tsum += __shfl_xor_sync(0xffffffffu, tsum, 1, 16);
            tsum += __shfl_xor_sync(0xffffffffu, tsum, 2, 16);
            tsum += __shfl_xor_sync(0xffffffffu, tsum, 4, 16);
            tsum += __shfl_xor_sync(0xffffffffu, tsum, 8, 16);

            l_run[i] = l_run[i] * sc_old + tsum;

            #pragma unroll
            for (int j = 0; j < 4; j++) accO[i][j] *= sc_old;
            #pragma unroll
            for (int j = 0; j < 4; j++)
                sP[(ty * 4 + i) * 68 + tx * 4 + j] = sc[i][j];
        }
        __syncthreads();

        #pragma unroll 4
        for (int kk = 0; kk < 64; kk += 4) {
            float p[4][4], vv[4][4];
            #pragma unroll
            for (int i = 0; i < 4; i++)
                *(float4*)p[i] = *(const float4*)&sP[(ty * 4 + i) * 68 + kk];
            #pragma unroll
            for (int r = 0; r < 4; r++)
                *(float4*)vv[r] = *(const float4*)&sV[(kk + r) * 68 + tx * 4];
            #pragma unroll
            for (int i = 0; i < 4; i++)
                #pragma unroll
                for (int r = 0; r < 4; r++)
                    #pragma unroll
                    for (int j = 0; j < 4; j++)
                        accO[i][j] = fmaf(p[i][r], vv[r][j], accO[i][j]);
        }
    }

    // normalize + write ctx as bf16 hi/lo, layout [m][D]
    #pragma unroll
    for (int i = 0; i < 4; i++) {
        float inv = 1.0f / l_run[i];
        int m = b * SEQ + q0 + ty * 4 + i;
        size_t off = (size_t)m * D_MODEL + h * HD + tx * 4;
        float v0 = accO[i][0] * inv, v1 = accO[i][1] * inv;
        float v2 = accO[i][2] * inv, v3 = accO[i][3] * inv;
        __nv_bfloat16 h0 = __float2bfloat16(v0), h1 = __float2bfloat16(v1);
        __nv_bfloat16 h2 = __float2bfloat16(v2), h3 = __float2bfloat16(v3);
        __nv_bfloat16 l0 = __float2bfloat16(v0 - __bfloat162float(h0));
        __nv_bfloat16 l1 = __float2bfloat16(v1 - __bfloat162float(h1));
        __nv_bfloat16 l2 = __float2bfloat16(v2 - __bfloat162float(h2));
        __nv_bfloat16 l3 = __float2bfloat16(v3 - __bfloat162float(h3));
        __nv_bfloat162 a, c, d, e;
        a.x = h0; a.y = h1;  c.x = h2; c.y = h3;
        d.x = l0; d.y = l1;  e.x = l2; e.y = l3;
        *(__nv_bfloat162*)(g_ch + off)     = a;
        *(__nv_bfloat162*)(g_ch + off + 2) = c;
        *(__nv_bfloat162*)(g_cl + off)     = d;
        *(__nv_bfloat162*)(g_cl + off + 2) = e;
    }
}

// ===========================================================================
extern "C" void kernel_launch(void* const* d_in, const int* in_sizes, int n_in,
                              void* d_out, int out_size)
{
    (void)in_sizes; (void)n_in; (void)out_size;
    const float* x  = (const float*)d_in[0];
    const float* Wq = (const float*)d_in[1];
    const float* Wk = (const float*)d_in[2];
    const float* Wv = (const float*)d_in[3];
    const float* Wo = (const float*)d_in[4];
    const float* bo = (const float*)d_in[5];
    float* out = (float*)d_out;

    cudaFuncSetAttribute(attn_kernel,
                         cudaFuncAttributeMaxDynamicSharedMemorySize, ATTN_SMEM);
    cudaFuncSetAttribute(qkv_mma_kernel,
                         cudaFuncAttributeMaxDynamicSharedMemorySize, GEMM_DYN);
    cudaFuncSetAttribute(out_mma_kernel,
                         cudaFuncAttributeMaxDynamicSharedMemorySize, GEMM_DYN);

    cvt_x_kernel<<<MTOT * D_MODEL / 1024, 256>>>(x);
    cvt_w_kernel<<<dim3(32, 32, 4), 256>>>(Wq, Wk, Wv, Wo);

    qkv_mma_kernel<<<dim3(D_MODEL / TN, MTOT / TM, 3), 256, GEMM_DYN>>>();

    attn_kernel<<<dim3(SEQ / 64, BATCH * NHEADS), 256, ATTN_SMEM>>>();

    out_mma_kernel<<<dim3(D_MODEL / TN, MTOT / TM), 256, GEMM_DYN>>>(bo, out);
}

// round 8
// speedup vs baseline: 1.5859x; 1.5859x over previous
#include <cuda_runtime.h>
#include <cuda_bf16.h>
#include <cstdint>

#define D_MODEL 1024
#define NHEADS  16
#define HD      64
#define BATCH   4
#define SEQ     2048
#define MTOT    (BATCH*SEQ)   // 8192

// ---- mma.sync GEMM tiling ----
#define TM 128
#define TN 128
#define BK 32
#define NCHUNK (D_MODEL/BK)   // 32
#define LROW 40               // padded row length (elements) -> 80 bytes
#define MAT_BYTES (128*LROW*2)            // 10240
#define OFF_AH 0
#define OFF_AL (MAT_BYTES)
#define OFF_BH (2*MAT_BYTES)
#define OFF_BL (3*MAT_BYTES)
#define STAGE_BYTES (4*MAT_BYTES)         // 40960
#define GEMM_DYN (2*STAGE_BYTES)          // 81920

// ---- scratch (no cudaMalloc allowed); 16B-aligned ----
__device__ __align__(16) float g_q[MTOT*D_MODEL];                 // [bh][s][64]
__device__ __align__(16) float g_k[MTOT*D_MODEL];                 // [bh][s][64]
__device__ __align__(16) float g_v[MTOT*D_MODEL];                 // [bh][s][64]
__device__ __align__(16) __nv_bfloat16 g_xh[MTOT*D_MODEL];        // X split
__device__ __align__(16) __nv_bfloat16 g_xl[MTOT*D_MODEL];
__device__ __align__(16) __nv_bfloat16 g_wh[4*D_MODEL*D_MODEL];   // W^T split
__device__ __align__(16) __nv_bfloat16 g_wl[4*D_MODEL*D_MODEL];
__device__ __align__(16) __nv_bfloat16 g_ch[MTOT*D_MODEL];        // ctx split [m][D]
__device__ __align__(16) __nv_bfloat16 g_cl[MTOT*D_MODEL];

// ===========================================================================
// PTX helpers (baseline PTX only)
// ===========================================================================
__device__ __forceinline__ uint32_t smem_u32(const void* p) {
    uint32_t a;
    asm("{ .reg .u64 t; cvta.to.shared.u64 t, %1; cvt.u32.u64 %0, t; }"
        : "=r"(a) : "l"(p));
    return a;
}
__device__ __forceinline__ void cp16(uint32_t dst, const void* src) {
    asm volatile("cp.async.cg.shared.global [%0], [%1], 16;"
                 :: "r"(dst), "l"(src) : "memory");
}
__device__ __forceinline__ void ldsm4(uint32_t* r, uint32_t addr) {
    asm volatile("ldmatrix.sync.aligned.m8n8.x4.shared.b16 {%0,%1,%2,%3}, [%4];"
                 : "=r"(r[0]), "=r"(r[1]), "=r"(r[2]), "=r"(r[3]) : "r"(addr));
}
__device__ __forceinline__ void ldsm2(uint32_t* r, uint32_t addr) {
    asm volatile("ldmatrix.sync.aligned.m8n8.x2.shared.b16 {%0,%1}, [%2];"
                 : "=r"(r[0]), "=r"(r[1]) : "r"(addr));
}
__device__ __forceinline__ void mma16816(float* c, const uint32_t* a, const uint32_t* b) {
    asm volatile(
        "mma.sync.aligned.m16n8k16.row.col.f32.bf16.bf16.f32 "
        "{%0,%1,%2,%3}, {%4,%5,%6,%7}, {%8,%9}, {%0,%1,%2,%3};"
        : "+f"(c[0]), "+f"(c[1]), "+f"(c[2]), "+f"(c[3])
        : "r"(a[0]), "r"(a[1]), "r"(a[2]), "r"(a[3]), "r"(b[0]), "r"(b[1]));
}

// ===========================================================================
// Convert kernels
// ===========================================================================
__global__ __launch_bounds__(256) void cvt_x_kernel(const float* __restrict__ X)
{
    size_t i = ((size_t)blockIdx.x * 256 + threadIdx.x) * 4;
    float4 v = *(const float4*)(X + i);
    __nv_bfloat16 h0 = __float2bfloat16(v.x), h1 = __float2bfloat16(v.y);
    __nv_bfloat16 h2 = __float2bfloat16(v.z), h3 = __float2bfloat16(v.w);
    __nv_bfloat16 l0 = __float2bfloat16(v.x - __bfloat162float(h0));
    __nv_bfloat16 l1 = __float2bfloat16(v.y - __bfloat162float(h1));
    __nv_bfloat16 l2 = __float2bfloat16(v.z - __bfloat162float(h2));
    __nv_bfloat16 l3 = __float2bfloat16(v.w - __bfloat162float(h3));
    __nv_bfloat162 a, b, c, d;
    a.x = h0; a.y = h1;  b.x = h2; b.y = h3;
    c.x = l0; c.y = l1;  d.x = l2; d.y = l3;
    *(__nv_bfloat162*)(g_xh + i)     = a;
    *(__nv_bfloat162*)(g_xh + i + 2) = b;
    *(__nv_bfloat162*)(g_xl + i)     = c;
    *(__nv_bfloat162*)(g_xl + i + 2) = d;
}

// transpose + split: Wt[n][k] = W[k][n]
__global__ __launch_bounds__(256) void cvt_w_kernel(
    const float* __restrict__ Wq, const float* __restrict__ Wk,
    const float* __restrict__ Wv, const float* __restrict__ Wo)
{
    __shared__ float t[32][33];
    const float* W = (blockIdx.z == 0) ? Wq : (blockIdx.z == 1) ? Wk
                   : (blockIdx.z == 2) ? Wv : Wo;
    int n0 = blockIdx.x * 32, k0 = blockIdx.y * 32;
    int c = threadIdx.x & 31, r8 = threadIdx.x >> 5;
    #pragma unroll
    for (int it = 0; it < 4; it++)
        t[r8 + it * 8][c] = W[(size_t)(k0 + r8 + it * 8) * D_MODEL + n0 + c];
    __syncthreads();
    __nv_bfloat16* oh = g_wh + (size_t)blockIdx.z * D_MODEL * D_MODEL;
    __nv_bfloat16* ol = g_wl + (size_t)blockIdx.z * D_MODEL * D_MODEL;
    #pragma unroll
    for (int it = 0; it < 4; it++) {
        int n = n0 + r8 + it * 8;
        float v = t[c][r8 + it * 8];
        __nv_bfloat16 h = __float2bfloat16(v);
        __nv_bfloat16 l = __float2bfloat16(v - __bfloat162float(h));
        oh[(size_t)n * D_MODEL + k0 + c] = h;
        ol[(size_t)n * D_MODEL + k0 + c] = l;
    }
}

// ===========================================================================
// bf16 mma.sync GEMM, hi/lo split, fp32 accum.
// ===========================================================================
__device__ __forceinline__ void stage_tile(uint32_t sbase,
                                           const __nv_bfloat16* __restrict__ G,
                                           int r0, int k0, int tid)
{
    int row = tid >> 1;          // 0..127
    int cb  = (tid & 1) * 2;     // 16B-chunk base: 0 or 2
    const __nv_bfloat16* gp = G + (size_t)(r0 + row) * D_MODEL + k0 + cb * 8;
    uint32_t so = sbase + (uint32_t)row * (LROW * 2) + (uint32_t)cb * 16;
    cp16(so,      gp);
    cp16(so + 16, gp + 8);
}

__device__ __forceinline__ void gemm_mainloop(
    const __nv_bfloat16* __restrict__ Ah, const __nv_bfloat16* __restrict__ Al,
    const __nv_bfloat16* __restrict__ Bh, const __nv_bfloat16* __restrict__ Bl,
    int m0, int n0, float acc[4][4][4])
{
    extern __shared__ __align__(16) char dyn[];
    const int tid = threadIdx.x;
    const int wid = tid >> 5, lane = tid & 31;
    const int wm = wid >> 2, wn = wid & 3;        // 2 x 4 warp grid
    const uint32_t sb = smem_u32(dyn);

    const uint32_t a_off = (uint32_t)(wm * 64 + (lane & 15)) * (LROW * 2)
                         + (uint32_t)(lane >> 4) * 16;
    const uint32_t b_off = (uint32_t)(wn * 32 + (lane & 7)) * (LROW * 2)
                         + (uint32_t)((lane >> 3) & 1) * 16;

    #pragma unroll
    for (int mt = 0; mt < 4; mt++)
        #pragma unroll
        for (int nt = 0; nt < 4; nt++)
            #pragma unroll
            for (int r = 0; r < 4; r++) acc[mt][nt][r] = 0.f;

    stage_tile(sb + OFF_AH, Ah, m0, 0, tid);
    stage_tile(sb + OFF_AL, Al, m0, 0, tid);
    stage_tile(sb + OFF_BH, Bh, n0, 0, tid);
    stage_tile(sb + OFF_BL, Bl, n0, 0, tid);
    asm volatile("cp.async.commit_group;" ::: "memory");

    for (int i = 0; i < NCHUNK; i++) {
        const uint32_t cur = sb + (uint32_t)(i & 1) * STAGE_BYTES;
        if (i + 1 < NCHUNK) {
            const uint32_t nxt = sb + (uint32_t)((i + 1) & 1) * STAGE_BYTES;
            const int k0 = (i + 1) * BK;
            stage_tile(nxt + OFF_AH, Ah, m0, k0, tid);
            stage_tile(nxt + OFF_AL, Al, m0, k0, tid);
            stage_tile(nxt + OFF_BH, Bh, n0, k0, tid);
            stage_tile(nxt + OFF_BL, Bl, n0, k0, tid);
            asm volatile("cp.async.commit_group;" ::: "memory");
            asm volatile("cp.async.wait_group 1;" ::: "memory");
        } else {
            asm volatile("cp.async.wait_group 0;" ::: "memory");
        }
        __syncthreads();

        #pragma unroll
        for (int kk = 0; kk < 2; kk++) {
            const uint32_t ko = (uint32_t)kk * 32;
            uint32_t afh[4][4], afl[4][4], bfh[4][2], bfl[4][2];
            #pragma unroll
            for (int mt = 0; mt < 4; mt++) {
                ldsm4(afh[mt], cur + OFF_AH + a_off + (uint32_t)mt * 16 * (LROW * 2) + ko);
                ldsm4(afl[mt], cur + OFF_AL + a_off + (uint32_t)mt * 16 * (LROW * 2) + ko);
            }
            #pragma unroll
            for (int nt = 0; nt < 4; nt++) {
                ldsm2(bfh[nt], cur + OFF_BH + b_off + (uint32_t)nt * 8 * (LROW * 2) + ko);
                ldsm2(bfl[nt], cur + OFF_BL + b_off + (uint32_t)nt * 8 * (LROW * 2) + ko);
            }
            #pragma unroll
            for (int mt = 0; mt < 4; mt++)
                #pragma unroll
                for (int nt = 0; nt < 4; nt++) {
                    mma16816(acc[mt][nt], afh[mt], bfh[nt]);
                    mma16816(acc[mt][nt], afh[mt], bfl[nt]);
                    mma16816(acc[mt][nt], afl[mt], bfh[nt]);
                }
        }
        __syncthreads();
    }
}

// QKV: scatter fp32 to [bh][s][64]
__global__ __launch_bounds__(256, 1) void qkv_mma_kernel()
{
    const int z  = blockIdx.z;
    const int m0 = blockIdx.y * TM, n0 = blockIdx.x * TN;
    const __nv_bfloat16* Bh = g_wh + (size_t)z * D_MODEL * D_MODEL;
    const __nv_bfloat16* Bl = g_wl + (size_t)z * D_MODEL * D_MODEL;
    float* Out = (z == 0) ? g_q : (z == 1) ? g_k : g_v;

    float acc[4][4][4];
    gemm_mainloop(g_xh, g_xl, Bh, Bl, m0, n0, acc);

    const int tid = threadIdx.x;
    const int wid = tid >> 5, lane = tid & 31;
    const int wm = wid >> 2, wn = wid & 3;
    const int er = lane >> 2, ec = (lane & 3) * 2;

    #pragma unroll
    for (int mt = 0; mt < 4; mt++) {
        const int mrow = m0 + wm * 64 + mt * 16 + er;
        const int b = mrow >> 11, s = mrow & (SEQ - 1);
        #pragma unroll
        for (int nt = 0; nt < 4; nt++) {
            const int ncol = n0 + wn * 32 + nt * 8 + ec;
            const int h = ncol >> 6, hd = ncol & 63;
            float* d0 = Out + (((size_t)(b * NHEADS + h) * SEQ) + s) * HD + hd;
            float2 lo, hi;
            lo.x = acc[mt][nt][0]; lo.y = acc[mt][nt][1];
            hi.x = acc[mt][nt][2]; hi.y = acc[mt][nt][3];
            *(float2*)d0              = lo;
            *(float2*)(d0 + 8 * HD)   = hi;   // row +8 (s+8), same (b,h)
        }
    }
}

// Output projection: plain [m][D] + bias
__global__ __launch_bounds__(256, 1) void out_mma_kernel(
    const float* __restrict__ bo, float* __restrict__ out)
{
    const int m0 = blockIdx.y * TM, n0 = blockIdx.x * TN;
    const __nv_bfloat16* Bh = g_wh + (size_t)3 * D_MODEL * D_MODEL;
    const __nv_bfloat16* Bl = g_wl + (size_t)3 * D_MODEL * D_MODEL;

    float acc[4][4][4];
    gemm_mainloop(g_ch, g_cl, Bh, Bl, m0, n0, acc);

    const int tid = threadIdx.x;
    const int wid = tid >> 5, lane = tid & 31;
    const int wm = wid >> 2, wn = wid & 3;
    const int er = lane >> 2, ec = (lane & 3) * 2;

    #pragma unroll
    for (int mt = 0; mt < 4; mt++) {
        const int mrow = m0 + wm * 64 + mt * 16 + er;
        #pragma unroll
        for (int nt = 0; nt < 4; nt++) {
            const int ncol = n0 + wn * 32 + nt * 8 + ec;
            float2 lo, hi;
            lo.x = acc[mt][nt][0] + bo[ncol];
            lo.y = acc[mt][nt][1] + bo[ncol + 1];
            hi.x = acc[mt][nt][2] + bo[ncol];
            hi.y = acc[mt][nt][3] + bo[ncol + 1];
            *(float2*)(out + (size_t)mrow * D_MODEL + ncol)       = lo;
            *(float2*)(out + (size_t)(mrow + 8) * D_MODEL + ncol) = hi;
        }
    }
}

// ===========================================================================
// Flash attention, fp32, causal — R2's proven 64x64 shape on contiguous
// [bh][s][64] q/k/v; ctx written as bf16 hi/lo at [m][D] (R5's epilogue).
// ===========================================================================
#define ATTN_SMEM (4 * 64 * 68 * 4)   // 69632 B (R5-proven level)

__global__ __launch_bounds__(256) void attn_kernel()
{
    extern __shared__ float sm[];
    float* sQt = sm;                // [64][68]  d-major Q (pre-scaled)
    float* sKt = sm + 64 * 68;      // [64][68]  d-major K
    float* sV  = sm + 2 * 64 * 68;  // [64][68]  k-major V
    float* sP  = sm + 3 * 64 * 68;  // [64][68]  row-major P

    const int tid = threadIdx.x;
    const int tx  = tid & 15, ty = tid >> 4;
    const int bh  = blockIdx.y;     // b*16 + h
    const int qt  = blockIdx.x;
    const int q0  = qt * 64;
    const int b   = bh >> 4, h = bh & 15;

    const float* Qg = g_q + (size_t)bh * SEQ * HD;
    const float* Kg = g_k + (size_t)bh * SEQ * HD;
    const float* Vg = g_v + (size_t)bh * SEQ * HD;

    // Q tile -> sQt (transposed, scaled by 1/sqrt(64) = 0.125)
    {
        const int row = tid >> 2;            // 0..63
        const int dg  = (tid & 3) * 16;      // 0,16,32,48
        const float* src = Qg + (size_t)(q0 + row) * HD + dg;
        #pragma unroll
        for (int v = 0; v < 4; v++) {
            float4 t = *(const float4*)(src + v * 4);
            sQt[(dg + v * 4 + 0) * 68 + row] = t.x * 0.125f;
            sQt[(dg + v * 4 + 1) * 68 + row] = t.y * 0.125f;
            sQt[(dg + v * 4 + 2) * 68 + row] = t.z * 0.125f;
            sQt[(dg + v * 4 + 3) * 68 + row] = t.w * 0.125f;
        }
    }

    float accO[4][4];
    float m_run[4], l_run[4];
    #pragma unroll
    for (int i = 0; i < 4; i++) {
        m_run[i] = -1e30f;
        l_run[i] = 0.f;
        #pragma unroll
        for (int j = 0; j < 4; j++) accO[i][j] = 0.f;
    }

    for (int t = 0; t <= qt; t++) {
        const int k0 = t * 64;
        __syncthreads();   // previous tile fully consumed; also fences the Q fill

        // K (transposed) + V tiles
        {
            const int row = tid >> 2;
            const int dg  = (tid & 3) * 16;
            const float* ks = Kg + (size_t)(k0 + row) * HD + dg;
            const float* vs = Vg + (size_t)(k0 + row) * HD + dg;
            #pragma unroll
            for (int v = 0; v < 4; v++) {
                float4 tk = *(const float4*)(ks + v * 4);
                sKt[(dg + v * 4 + 0) * 68 + row] = tk.x;
                sKt[(dg + v * 4 + 1) * 68 + row] = tk.y;
                sKt[(dg + v * 4 + 2) * 68 + row] = tk.z;
                sKt[(dg + v * 4 + 3) * 68 + row] = tk.w;
                *(float4*)&sV[row * 68 + dg + v * 4] = *(const float4*)(vs + v * 4);
            }
        }
        __syncthreads();

        // S = (Q*scale) @ K^T  (4x4 per thread)
        float sc[4][4];
        #pragma unroll
        for (int i = 0; i < 4; i++)
            #pragma unroll
            for (int j = 0; j < 4; j++) sc[i][j] = 0.f;

        #pragma unroll 16
        for (int d = 0; d < 64; d++) {
            float a[4], bb[4];
            *(float4*)a  = *(const float4*)&sQt[d * 68 + ty * 4];
            *(float4*)bb = *(const float4*)&sKt[d * 68 + tx * 4];
            #pragma unroll
            for (int i = 0; i < 4; i++)
                #pragma unroll
                for (int j = 0; j < 4; j++)
                    sc[i][j] = fmaf(a[i], bb[j], sc[i][j]);
        }

        // causal mask on the diagonal tile
        if (t == qt) {
            #pragma unroll
            for (int i = 0; i < 4; i++)
                #pragma unroll
                for (int j = 0; j < 4; j++)
                    if (tx * 4 + j > ty * 4 + i) sc[i][j] = -1e30f;
        }

        // online softmax (row stats replicated across the 16-lane row group)
        #pragma unroll
        for (int i = 0; i < 4; i++) {
            float tm = fmaxf(fmaxf(sc[i][0], sc[i][1]), fmaxf(sc[i][2], sc[i][3]));
            tm = fmaxf(tm, __shfl_xor_sync(0xffffffffu, tm, 1, 16));
            tm = fmaxf(tm, __shfl_xor_sync(0xffffffffu, tm, 2, 16));
            tm = fmaxf(tm, __shfl_xor_sync(0xffffffffu, tm, 4, 16));
            tm = fmaxf(tm, __shfl_xor_sync(0xffffffffu, tm, 8, 16));

            float mnew   = fmaxf(m_run[i], tm);
            float sc_old = __expf(m_run[i] - mnew);
            m_run[i] = mnew;

            float tsum = 0.f;
            #pragma unroll
            for (int j = 0; j < 4; j++) {
                float p = __expf(sc[i][j] - mnew);
                sc[i][j] = p;
                tsum += p;
            }
            tsum += __shfl_xor_sync(0xffffffffu, tsum, 1, 16);
            tsum += __shfl_xor_sync(0xffffffffu, tsum, 2, 16);
            tsum += __shfl_xor_sync(0xffffffffu, tsum, 4, 16);
            tsum += __shfl_xor_sync(0xffffffffu, tsum, 8, 16);

            l_run[i] = l_run[i] * sc_old + tsum;

            #pragma unroll
            for (int j = 0; j < 4; j++) accO[i][j] *= sc_old;
            #pragma unroll
            for (int j = 0; j < 4; j++)
                sP[(ty * 4 + i) * 68 + tx * 4 + j] = sc[i][j];
        }
        __syncthreads();

        // O += P @ V  (kk chunked by 4 -> float4 loads both sides)
        #pragma unroll 4
        for (int kk = 0; kk < 64; kk += 4) {
            float p[4][4], vv[4][4];
            #pragma unroll
            for (int i = 0; i < 4; i++)
                *(float4*)p[i] = *(const float4*)&sP[(ty * 4 + i) * 68 + kk];
            #pragma unroll
            for (int r = 0; r < 4; r++)
                *(float4*)vv[r] = *(const float4*)&sV[(kk + r) * 68 + tx * 4];
            #pragma unroll
            for (int i = 0; i < 4; i++)
                #pragma unroll
                for (int r = 0; r < 4; r++)
                    #pragma unroll
                    for (int j = 0; j < 4; j++)
                        accO[i][j] = fmaf(p[i][r], vv[r][j], accO[i][j]);
        }
    }

    // normalize + write ctx as bf16 hi/lo, layout [m][D]
    #pragma unroll
    for (int i = 0; i < 4; i++) {
        float inv = 1.0f / l_run[i];
        int m = b * SEQ + q0 + ty * 4 + i;
        size_t off = (size_t)m * D_MODEL + h * HD + tx * 4;
        float v0 = accO[i][0] * inv, v1 = accO[i][1] * inv;
        float v2 = accO[i][2] * inv, v3 = accO[i][3] * inv;
        __nv_bfloat16 h0 = __float2bfloat16(v0), h1 = __float2bfloat16(v1);
        __nv_bfloat16 h2 = __float2bfloat16(v2), h3 = __float2bfloat16(v3);
        __nv_bfloat16 l0 = __float2bfloat16(v0 - __bfloat162float(h0));
        __nv_bfloat16 l1 = __float2bfloat16(v1 - __bfloat162float(h1));
        __nv_bfloat16 l2 = __float2bfloat16(v2 - __bfloat162float(h2));
        __nv_bfloat16 l3 = __float2bfloat16(v3 - __bfloat162float(h3));
        __nv_bfloat162 a, c, d, e;
        a.x = h0; a.y = h1;  c.x = h2; c.y = h3;
        d.x = l0; d.y = l1;  e.x = l2; e.y = l3;
        *(__nv_bfloat162*)(g_ch + off)     = a;
        *(__nv_bfloat162*)(g_ch + off + 2) = c;
        *(__nv_bfloat162*)(g_cl + off)     = d;
        *(__nv_bfloat162*)(g_cl + off + 2) = e;
    }
}

// ===========================================================================
extern "C" void kernel_launch(void* const* d_in, const int* in_sizes, int n_in,
                              void* d_out, int out_size)
{
    (void)in_sizes; (void)n_in; (void)out_size;
    const float* x  = (const float*)d_in[0];
    const float* Wq = (const float*)d_in[1];
    const float* Wk = (const float*)d_in[2];
    const float* Wv = (const float*)d_in[3];
    const float* Wo = (const float*)d_in[4];
    const float* bo = (const float*)d_in[5];
    float* out = (float*)d_out;

    cudaFuncSetAttribute(attn_kernel,
                         cudaFuncAttributeMaxDynamicSharedMemorySize, ATTN_SMEM);
    cudaFuncSetAttribute(qkv_mma_kernel,
                         cudaFuncAttributeMaxDynamicSharedMemorySize, GEMM_DYN);
    cudaFuncSetAttribute(out_mma_kernel,
                         cudaFuncAttributeMaxDynamicSharedMemorySize, GEMM_DYN);

    cvt_x_kernel<<<MTOT * D_MODEL / 1024, 256>>>(x);
    cvt_w_kernel<<<dim3(32, 32, 4), 256>>>(Wq, Wk, Wv, Wo);

    qkv_mma_kernel<<<dim3(D_MODEL / TN, MTOT / TM, 3), 256, GEMM_DYN>>>();

    attn_kernel<<<dim3(SEQ / 64, BATCH * NHEADS), 256, ATTN_SMEM>>>();

    out_mma_kernel<<<dim3(D_MODEL / TN, MTOT / TM), 256, GEMM_DYN>>>(bo, out);
}

// round 9
// speedup vs baseline: 2.3569x; 1.4861x over previous
#include <cuda_runtime.h>
#include <cuda_bf16.h>
#include <cstdint>

#define D_MODEL 1024
#define NHEADS  16
#define HD      64
#define BATCH   4
#define SEQ     2048
#define MTOT    (BATCH*SEQ)   // 8192

// ---- mma.sync GEMM tiling ----
#define TM 128
#define TN 128
#define BK 32
#define NCHUNK (D_MODEL/BK)   // 32
#define LROW 40               // padded row length (elements) -> 80 bytes
#define MAT_BYTES (128*LROW*2)            // 10240
#define OFF_AH 0
#define OFF_AL (MAT_BYTES)
#define OFF_BH (2*MAT_BYTES)
#define OFF_BL (3*MAT_BYTES)
#define STAGE_BYTES (4*MAT_BYTES)         // 40960
#define GEMM_DYN (2*STAGE_BYTES)          // 81920

// ---- scratch (no cudaMalloc allowed); 16B-aligned ----
__device__ __align__(16) __nv_bfloat16 g_qh[MTOT*D_MODEL];  // [bh][s][64] hi (pre-scaled)
__device__ __align__(16) __nv_bfloat16 g_ql[MTOT*D_MODEL];  // lo
__device__ __align__(16) __nv_bfloat16 g_kh[MTOT*D_MODEL];
__device__ __align__(16) __nv_bfloat16 g_kl[MTOT*D_MODEL];
__device__ __align__(16) __nv_bfloat16 g_vh[MTOT*D_MODEL];
__device__ __align__(16) __nv_bfloat16 g_vl[MTOT*D_MODEL];
__device__ __align__(16) __nv_bfloat16 g_xh[MTOT*D_MODEL];        // X split
__device__ __align__(16) __nv_bfloat16 g_xl[MTOT*D_MODEL];
__device__ __align__(16) __nv_bfloat16 g_wh[4*D_MODEL*D_MODEL];   // W^T split
__device__ __align__(16) __nv_bfloat16 g_wl[4*D_MODEL*D_MODEL];
__device__ __align__(16) __nv_bfloat16 g_ch[MTOT*D_MODEL];        // ctx split [m][D]
__device__ __align__(16) __nv_bfloat16 g_cl[MTOT*D_MODEL];

// ===========================================================================
// PTX helpers (baseline PTX only)
// ===========================================================================
__device__ __forceinline__ uint32_t smem_u32(const void* p) {
    uint32_t a;
    asm("{ .reg .u64 t; cvta.to.shared.u64 t, %1; cvt.u32.u64 %0, t; }"
        : "=r"(a) : "l"(p));
    return a;
}
__device__ __forceinline__ void cp16(uint32_t dst, const void* src) {
    asm volatile("cp.async.cg.shared.global [%0], [%1], 16;"
                 :: "r"(dst), "l"(src) : "memory");
}
__device__ __forceinline__ void ldsm4(uint32_t* r, uint32_t addr) {
    asm volatile("ldmatrix.sync.aligned.m8n8.x4.shared.b16 {%0,%1,%2,%3}, [%4];"
                 : "=r"(r[0]), "=r"(r[1]), "=r"(r[2]), "=r"(r[3]) : "r"(addr));
}
__device__ __forceinline__ void ldsm2(uint32_t* r, uint32_t addr) {
    asm volatile("ldmatrix.sync.aligned.m8n8.x2.shared.b16 {%0,%1}, [%2];"
                 : "=r"(r[0]), "=r"(r[1]) : "r"(addr));
}
__device__ __forceinline__ void ldsm4t(uint32_t* r, uint32_t addr) {
    asm volatile("ldmatrix.sync.aligned.m8n8.x4.trans.shared.b16 {%0,%1,%2,%3}, [%4];"
                 : "=r"(r[0]), "=r"(r[1]), "=r"(r[2]), "=r"(r[3]) : "r"(addr));
}
__device__ __forceinline__ void mma16816(float* c, const uint32_t* a, const uint32_t* b) {
    asm volatile(
        "mma.sync.aligned.m16n8k16.row.col.f32.bf16.bf16.f32 "
        "{%0,%1,%2,%3}, {%4,%5,%6,%7}, {%8,%9}, {%0,%1,%2,%3};"
        : "+f"(c[0]), "+f"(c[1]), "+f"(c[2]), "+f"(c[3])
        : "r"(a[0]), "r"(a[1]), "r"(a[2]), "r"(a[3]), "r"(b[0]), "r"(b[1]));
}
__device__ __forceinline__ void mma2(float* c, const uint32_t* a, uint32_t b0, uint32_t b1) {
    asm volatile(
        "mma.sync.aligned.m16n8k16.row.col.f32.bf16.bf16.f32 "
        "{%0,%1,%2,%3}, {%4,%5,%6,%7}, {%8,%9}, {%0,%1,%2,%3};"
        : "+f"(c[0]), "+f"(c[1]), "+f"(c[2]), "+f"(c[3])
        : "r"(a[0]), "r"(a[1]), "r"(a[2]), "r"(a[3]), "r"(b0), "r"(b1));
}
// split (x,y) fp32 -> packed bf16 hi pair + lo pair
__device__ __forceinline__ void split2(float x, float y, uint32_t& hi, uint32_t& lo) {
    __nv_bfloat16 hx = __float2bfloat16(x), hy = __float2bfloat16(y);
    __nv_bfloat16 lx = __float2bfloat16(x - __bfloat162float(hx));
    __nv_bfloat16 ly = __float2bfloat16(y - __bfloat162float(hy));
    __nv_bfloat162 H, L;
    H.x = hx; H.y = hy; L.x = lx; L.y = ly;
    hi = *reinterpret_cast<uint32_t*>(&H);
    lo = *reinterpret_cast<uint32_t*>(&L);
}

// ===========================================================================
// Convert kernels
// ===========================================================================
__global__ __launch_bounds__(256) void cvt_x_kernel(const float* __restrict__ X)
{
    size_t i = ((size_t)blockIdx.x * 256 + threadIdx.x) * 4;
    float4 v = *(const float4*)(X + i);
    uint32_t h0, l0, h1, l1;
    split2(v.x, v.y, h0, l0);
    split2(v.z, v.w, h1, l1);
    *(uint32_t*)(g_xh + i)     = h0;
    *(uint32_t*)(g_xh + i + 2) = h1;
    *(uint32_t*)(g_xl + i)     = l0;
    *(uint32_t*)(g_xl + i + 2) = l1;
}

// transpose + split: Wt[n][k] = W[k][n]
__global__ __launch_bounds__(256) void cvt_w_kernel(
    const float* __restrict__ Wq, const float* __restrict__ Wk,
    const float* __restrict__ Wv, const float* __restrict__ Wo)
{
    __shared__ float t[32][33];
    const float* W = (blockIdx.z == 0) ? Wq : (blockIdx.z == 1) ? Wk
                   : (blockIdx.z == 2) ? Wv : Wo;
    int n0 = blockIdx.x * 32, k0 = blockIdx.y * 32;
    int c = threadIdx.x & 31, r8 = threadIdx.x >> 5;
    #pragma unroll
    for (int it = 0; it < 4; it++)
        t[r8 + it * 8][c] = W[(size_t)(k0 + r8 + it * 8) * D_MODEL + n0 + c];
    __syncthreads();
    __nv_bfloat16* oh = g_wh + (size_t)blockIdx.z * D_MODEL * D_MODEL;
    __nv_bfloat16* ol = g_wl + (size_t)blockIdx.z * D_MODEL * D_MODEL;
    #pragma unroll
    for (int it = 0; it < 4; it++) {
        int n = n0 + r8 + it * 8;
        float v = t[c][r8 + it * 8];
        __nv_bfloat16 h = __float2bfloat16(v);
        __nv_bfloat16 l = __float2bfloat16(v - __bfloat162float(h));
        oh[(size_t)n * D_MODEL + k0 + c] = h;
        ol[(size_t)n * D_MODEL + k0 + c] = l;
    }
}

// ===========================================================================
// bf16 mma.sync GEMM, hi/lo split, fp32 accum. (unchanged, R8-proven)
// ===========================================================================
__device__ __forceinline__ void stage_tile(uint32_t sbase,
                                           const __nv_bfloat16* __restrict__ G,
                                           int r0, int k0, int tid)
{
    int row = tid >> 1;
    int cb  = (tid & 1) * 2;
    const __nv_bfloat16* gp = G + (size_t)(r0 + row) * D_MODEL + k0 + cb * 8;
    uint32_t so = sbase + (uint32_t)row * (LROW * 2) + (uint32_t)cb * 16;
    cp16(so,      gp);
    cp16(so + 16, gp + 8);
}

__device__ __forceinline__ void gemm_mainloop(
    const __nv_bfloat16* __restrict__ Ah, const __nv_bfloat16* __restrict__ Al,
    const __nv_bfloat16* __restrict__ Bh, const __nv_bfloat16* __restrict__ Bl,
    int m0, int n0, float acc[4][4][4])
{
    extern __shared__ __align__(16) char dyn[];
    const int tid = threadIdx.x;
    const int wid = tid >> 5, lane = tid & 31;
    const int wm = wid >> 2, wn = wid & 3;
    const uint32_t sb = smem_u32(dyn);

    const uint32_t a_off = (uint32_t)(wm * 64 + (lane & 15)) * (LROW * 2)
                         + (uint32_t)(lane >> 4) * 16;
    const uint32_t b_off = (uint32_t)(wn * 32 + (lane & 7)) * (LROW * 2)
                         + (uint32_t)((lane >> 3) & 1) * 16;

    #pragma unroll
    for (int mt = 0; mt < 4; mt++)
        #pragma unroll
        for (int nt = 0; nt < 4; nt++)
            #pragma unroll
            for (int r = 0; r < 4; r++) acc[mt][nt][r] = 0.f;

    stage_tile(sb + OFF_AH, Ah, m0, 0, tid);
    stage_tile(sb + OFF_AL, Al, m0, 0, tid);
    stage_tile(sb + OFF_BH, Bh, n0, 0, tid);
    stage_tile(sb + OFF_BL, Bl, n0, 0, tid);
    asm volatile("cp.async.commit_group;" ::: "memory");

    for (int i = 0; i < NCHUNK; i++) {
        const uint32_t cur = sb + (uint32_t)(i & 1) * STAGE_BYTES;
        if (i + 1 < NCHUNK) {
            const uint32_t nxt = sb + (uint32_t)((i + 1) & 1) * STAGE_BYTES;
            const int k0 = (i + 1) * BK;
            stage_tile(nxt + OFF_AH, Ah, m0, k0, tid);
            stage_tile(nxt + OFF_AL, Al, m0, k0, tid);
            stage_tile(nxt + OFF_BH, Bh, n0, k0, tid);
            stage_tile(nxt + OFF_BL, Bl, n0, k0, tid);
            asm volatile("cp.async.commit_group;" ::: "memory");
            asm volatile("cp.async.wait_group 1;" ::: "memory");
        } else {
            asm volatile("cp.async.wait_group 0;" ::: "memory");
        }
        __syncthreads();

        #pragma unroll
        for (int kk = 0; kk < 2; kk++) {
            const uint32_t ko = (uint32_t)kk * 32;
            uint32_t afh[4][4], afl[4][4], bfh[4][2], bfl[4][2];
            #pragma unroll
            for (int mt = 0; mt < 4; mt++) {
                ldsm4(afh[mt], cur + OFF_AH + a_off + (uint32_t)mt * 16 * (LROW * 2) + ko);
                ldsm4(afl[mt], cur + OFF_AL + a_off + (uint32_t)mt * 16 * (LROW * 2) + ko);
            }
            #pragma unroll
            for (int nt = 0; nt < 4; nt++) {
                ldsm2(bfh[nt], cur + OFF_BH + b_off + (uint32_t)nt * 8 * (LROW * 2) + ko);
                ldsm2(bfl[nt], cur + OFF_BL + b_off + (uint32_t)nt * 8 * (LROW * 2) + ko);
            }
            #pragma unroll
            for (int mt = 0; mt < 4; mt++)
                #pragma unroll
                for (int nt = 0; nt < 4; nt++) {
                    mma16816(acc[mt][nt], afh[mt], bfh[nt]);
                    mma16816(acc[mt][nt], afh[mt], bfl[nt]);
                    mma16816(acc[mt][nt], afl[mt], bfh[nt]);
                }
        }
        __syncthreads();
    }
}

// QKV: scatter bf16 hi/lo to [bh][s][64]; Q pre-scaled by 0.125
__global__ __launch_bounds__(256, 1) void qkv_mma_kernel()
{
    const int z  = blockIdx.z;
    const int m0 = blockIdx.y * TM, n0 = blockIdx.x * TN;
    const __nv_bfloat16* Bh = g_wh + (size_t)z * D_MODEL * D_MODEL;
    const __nv_bfloat16* Bl = g_wl + (size_t)z * D_MODEL * D_MODEL;
    __nv_bfloat16* Oh = (z == 0) ? g_qh : (z == 1) ? g_kh : g_vh;
    __nv_bfloat16* Ol = (z == 0) ? g_ql : (z == 1) ? g_kl : g_vl;
    const float scale = (z == 0) ? 0.125f : 1.0f;

    float acc[4][4][4];
    gemm_mainloop(g_xh, g_xl, Bh, Bl, m0, n0, acc);

    const int tid = threadIdx.x;
    const int wid = tid >> 5, lane = tid & 31;
    const int wm = wid >> 2, wn = wid & 3;
    const int er = lane >> 2, ec = (lane & 3) * 2;

    #pragma unroll
    for (int mt = 0; mt < 4; mt++) {
        const int mrow = m0 + wm * 64 + mt * 16 + er;
        const int b = mrow >> 11, s = mrow & (SEQ - 1);
        #pragma unroll
        for (int nt = 0; nt < 4; nt++) {
            const int ncol = n0 + wn * 32 + nt * 8 + ec;
            const int h = ncol >> 6, hd = ncol & 63;
            size_t o0 = (((size_t)(b * NHEADS + h) * SEQ) + s) * HD + hd;
            size_t o1 = o0 + (size_t)8 * HD;   // row s+8, same (b,h)
            uint32_t H0, L0, H1, L1;
            split2(acc[mt][nt][0] * scale, acc[mt][nt][1] * scale, H0, L0);
            split2(acc[mt][nt][2] * scale, acc[mt][nt][3] * scale, H1, L1);
            *(uint32_t*)(Oh + o0) = H0;  *(uint32_t*)(Ol + o0) = L0;
            *(uint32_t*)(Oh + o1) = H1;  *(uint32_t*)(Ol + o1) = L1;
        }
    }
}

// Output projection: plain [m][D] + bias (unchanged)
__global__ __launch_bounds__(256, 1) void out_mma_kernel(
    const float* __restrict__ bo, float* __restrict__ out)
{
    const int m0 = blockIdx.y * TM, n0 = blockIdx.x * TN;
    const __nv_bfloat16* Bh = g_wh + (size_t)3 * D_MODEL * D_MODEL;
    const __nv_bfloat16* Bl = g_wl + (size_t)3 * D_MODEL * D_MODEL;

    float acc[4][4][4];
    gemm_mainloop(g_ch, g_cl, Bh, Bl, m0, n0, acc);

    const int tid = threadIdx.x;
    const int wid = tid >> 5, lane = tid & 31;
    const int wm = wid >> 2, wn = wid & 3;
    const int er = lane >> 2, ec = (lane & 3) * 2;

    #pragma unroll
    for (int mt = 0; mt < 4; mt++) {
        const int mrow = m0 + wm * 64 + mt * 16 + er;
        #pragma unroll
        for (int nt = 0; nt < 4; nt++) {
            const int ncol = n0 + wn * 32 + nt * 8 + ec;
            float2 lo, hi;
            lo.x = acc[mt][nt][0] + bo[ncol];
            lo.y = acc[mt][nt][1] + bo[ncol + 1];
            hi.x = acc[mt][nt][2] + bo[ncol];
            hi.y = acc[mt][nt][3] + bo[ncol + 1];
            *(float2*)(out + (size_t)mrow * D_MODEL + ncol)       = lo;
            *(float2*)(out + (size_t)(mrow + 8) * D_MODEL + ncol) = hi;
        }
    }
}

// ===========================================================================
// Tensor-core flash attention, causal, bf16 hi/lo 3-pass, fp32 accum.
// Block: 128 thr / 4 warps; 64 q-rows per block (16 per warp); 64-key tiles.
// smem (bf16, stride 72): Qh,Ql (1 buf) + Kh,Kl,Vh,Vl (2 stages).
// ===========================================================================
#define AT_S 72
#define TILE_ELS (64*AT_S)                 // 4608
#define O_QH 0
#define O_QL (TILE_ELS)
#define O_KH (2*TILE_ELS)                  // + st*TILE_ELS
#define O_KL (4*TILE_ELS)
#define O_VH (6*TILE_ELS)
#define O_VL (8*TILE_ELS)
#define ATTN_DYN (10*TILE_ELS*2)           // 92160 B

__global__ __launch_bounds__(128) void attn_tc_kernel()
{
    extern __shared__ __align__(16) char smb[];
    const uint32_t sb = smem_u32(smb);

    const int tid = threadIdx.x, lane = tid & 31, w = tid >> 5;
    const int bh = blockIdx.y, qt = blockIdx.x;
    const int q0 = qt * 64;
    const int b = bh >> 4, h = bh & 15;
    const size_t hb = (size_t)bh * SEQ * HD;

    const int lrow = tid >> 1;            // 0..63
    const int lcb  = (tid & 1) * 32;      // element offset 0/32

    // ---- Q load (group 0) ----
    {
        size_t g = hb + (size_t)(q0 + lrow) * HD + lcb;
        uint32_t d = (uint32_t)(lrow * AT_S + lcb) * 2;
        #pragma unroll
        for (int u = 0; u < 4; u++) {
            cp16(sb + O_QH * 2 + d + u * 16, g_qh + g + u * 8);
            cp16(sb + O_QL * 2 + d + u * 16, g_ql + g + u * 8);
        }
    }
    // ---- K/V stage loader ----
    auto load_kv = [&](int st, int k0) {
        size_t g = hb + (size_t)(k0 + lrow) * HD + lcb;
        uint32_t d = (uint32_t)(lrow * AT_S + lcb) * 2 + (uint32_t)st * TILE_ELS * 2;
        #pragma unroll
        for (int u = 0; u < 4; u++) {
            cp16(sb + O_KH * 2 + d + u * 16, g_kh + g + u * 8);
            cp16(sb + O_KL * 2 + d + u * 16, g_kl + g + u * 8);
            cp16(sb + O_VH * 2 + d + u * 16, g_vh + g + u * 8);
            cp16(sb + O_VL * 2 + d + u * 16, g_vl + g + u * 8);
        }
    };
    load_kv(0, 0);
    asm volatile("cp.async.commit_group;" ::: "memory");

    float accO[8][4];
    float m_run[2] = {-1e30f, -1e30f}, l_run[2] = {0.f, 0.f};
    #pragma unroll
    for (int nt = 0; nt < 8; nt++)
        #pragma unroll
        for (int c = 0; c < 4; c++) accO[nt][c] = 0.f;

    // per-lane ldmatrix byte offsets
    const uint32_t qoff = ((uint32_t)(w * 16 + (lane & 15)) * AT_S + (uint32_t)(lane >> 4) * 8) * 2;
    const uint32_t koff = ((uint32_t)(lane & 15) * AT_S + (uint32_t)(lane >> 4) * 8) * 2;
    const uint32_t voff = ((uint32_t)(lane & 15) * AT_S + (uint32_t)(lane >> 4) * 8) * 2;

    for (int t = 0; t <= qt; t++) {
        const int st = t & 1;
        if (t < qt) {
            load_kv((t + 1) & 1, (t + 1) * 64);
            asm volatile("cp.async.commit_group;" ::: "memory");
            asm volatile("cp.async.wait_group 1;" ::: "memory");
        } else {
            asm volatile("cp.async.wait_group 0;" ::: "memory");
        }
        __syncthreads();

        const uint32_t sKh = sb + (O_KH + st * TILE_ELS) * 2;
        const uint32_t sKl = sb + (O_KL + st * TILE_ELS) * 2;
        const uint32_t sVh = sb + (O_VH + st * TILE_ELS) * 2;
        const uint32_t sVl = sb + (O_VL + st * TILE_ELS) * 2;

        // ---- S = Q @ K^T (3-pass hi/lo) ----
        float accS[8][4];
        #pragma unroll
        for (int nt = 0; nt < 8; nt++)
            #pragma unroll
            for (int c = 0; c < 4; c++) accS[nt][c] = 0.f;

        #pragma unroll
        for (int kk = 0; kk < 4; kk++) {
            uint32_t ah[4], al[4];
            ldsm4(ah, sb + O_QH * 2 + qoff + kk * 32);
            ldsm4(al, sb + O_QL * 2 + qoff + kk * 32);
            #pragma unroll
            for (int p = 0; p < 4; p++) {   // nt pair p -> nt = 2p, 2p+1
                uint32_t rh[4], rl[4];
                uint32_t ko2 = (uint32_t)(p * 16) * AT_S * 2 + koff + kk * 32;
                ldsm4(rh, sKh + ko2);
                ldsm4(rl, sKl + ko2);
                mma2(accS[2*p],   ah, rh[0], rh[2]);
                mma2(accS[2*p],   ah, rl[0], rl[2]);
                mma2(accS[2*p],   al, rh[0], rh[2]);
                mma2(accS[2*p+1], ah, rh[1], rh[3]);
                mma2(accS[2*p+1], ah, rl[1], rl[3]);
                mma2(accS[2*p+1], al, rh[1], rh[3]);
            }
        }

        // ---- causal mask (diagonal tile only; k0 == q0 there) ----
        if (t == qt) {
            #pragma unroll
            for (int nt = 0; nt < 8; nt++)
                #pragma unroll
                for (int c = 0; c < 4; c++) {
                    int rr  = w * 16 + (lane >> 2) + ((c >= 2) ? 8 : 0);
                    int col = nt * 8 + (lane & 3) * 2 + (c & 1);
                    if (col > rr) accS[nt][c] = -1e30f;
                }
        }

        // ---- online softmax on fragments (quad reductions) ----
        #pragma unroll
        for (int half = 0; half < 2; half++) {
            float mx = -1e30f;
            #pragma unroll
            for (int nt = 0; nt < 8; nt++)
                mx = fmaxf(mx, fmaxf(accS[nt][2*half], accS[nt][2*half+1]));
            mx = fmaxf(mx, __shfl_xor_sync(0xffffffffu, mx, 1, 4));
            mx = fmaxf(mx, __shfl_xor_sync(0xffffffffu, mx, 2, 4));

            float mnew  = fmaxf(m_run[half], mx);
            float alpha = __expf(m_run[half] - mnew);
            m_run[half] = mnew;

            float s = 0.f;
            #pragma unroll
            for (int nt = 0; nt < 8; nt++) {
                float p0 = __expf(accS[nt][2*half]   - mnew);
                float p1 = __expf(accS[nt][2*half+1] - mnew);
                accS[nt][2*half] = p0; accS[nt][2*half+1] = p1;
                s += p0 + p1;
            }
            s += __shfl_xor_sync(0xffffffffu, s, 1, 4);
            s += __shfl_xor_sync(0xffffffffu, s, 2, 4);
            l_run[half] = l_run[half] * alpha + s;

            #pragma unroll
            for (int nt = 0; nt < 8; nt++) {
                accO[nt][2*half]   *= alpha;
                accO[nt][2*half+1] *= alpha;
            }
        }

        // ---- O += P @ V (3-pass hi/lo; P packed from S frags; V via trans) ----
        #pragma unroll
        for (int kk = 0; kk < 4; kk++) {
            uint32_t pah[4], pal[4];
            split2(accS[2*kk][0],   accS[2*kk][1],   pah[0], pal[0]);
            split2(accS[2*kk][2],   accS[2*kk][3],   pah[1], pal[1]);
            split2(accS[2*kk+1][0], accS[2*kk+1][1], pah[2], pal[2]);
            split2(accS[2*kk+1][2], accS[2*kk+1][3], pah[3], pal[3]);
            #pragma unroll
            for (int p = 0; p < 4; p++) {   // nt pair -> d cols 2p*8, (2p+1)*8
                uint32_t vh4[4], vl4[4];
                uint32_t vo = (uint32_t)(kk * 16) * AT_S * 2 + (uint32_t)(p * 16) * 2 + voff;
                ldsm4t(vh4, sVh + vo);
                ldsm4t(vl4, sVl + vo);
                mma2(accO[2*p],   pah, vh4[0], vh4[1]);
                mma2(accO[2*p],   pah, vl4[0], vl4[1]);
                mma2(accO[2*p],   pal, vh4[0], vh4[1]);
                mma2(accO[2*p+1], pah, vh4[2], vh4[3]);
                mma2(accO[2*p+1], pah, vl4[2], vl4[3]);
                mma2(accO[2*p+1], pal, vh4[2], vh4[3]);
            }
        }
        __syncthreads();   // frees this stage's K/V buffers for reload
    }

    // ---- normalize + write ctx as bf16 hi/lo, layout [m][D] ----
    #pragma unroll
    for (int half = 0; half < 2; half++) {
        float inv = 1.0f / l_run[half];
        int m = b * SEQ + q0 + w * 16 + (lane >> 2) + half * 8;
        #pragma unroll
        for (int nt = 0; nt < 8; nt++) {
            int col = h * HD + nt * 8 + (lane & 3) * 2;
            size_t off = (size_t)m * D_MODEL + col;
            uint32_t H, L;
            split2(accO[nt][2*half] * inv, accO[nt][2*half+1] * inv, H, L);
            *(uint32_t*)(g_ch + off) = H;
            *(uint32_t*)(g_cl + off) = L;
        }
    }
}

// ===========================================================================
extern "C" void kernel_launch(void* const* d_in, const int* in_sizes, int n_in,
                              void* d_out, int out_size)
{
    (void)in_sizes; (void)n_in; (void)out_size;
    const float* x  = (const float*)d_in[0];
    const float* Wq = (const float*)d_in[1];
    const float* Wk = (const float*)d_in[2];
    const float* Wv = (const float*)d_in[3];
    const float* Wo = (const float*)d_in[4];
    const float* bo = (const float*)d_in[5];
    float* out = (float*)d_out;

    cudaFuncSetAttribute(attn_tc_kernel,
                         cudaFuncAttributeMaxDynamicSharedMemorySize, ATTN_DYN);
    cudaFuncSetAttribute(qkv_mma_kernel,
                         cudaFuncAttributeMaxDynamicSharedMemorySize, GEMM_DYN);
    cudaFuncSetAttribute(out_mma_kernel,
                         cudaFuncAttributeMaxDynamicSharedMemorySize, GEMM_DYN);

    cvt_x_kernel<<<MTOT * D_MODEL / 1024, 256>>>(x);
    cvt_w_kernel<<<dim3(32, 32, 4), 256>>>(Wq, Wk, Wv, Wo);

    qkv_mma_kernel<<<dim3(D_MODEL / TN, MTOT / TM, 3), 256, GEMM_DYN>>>();

    attn_tc_kernel<<<dim3(SEQ / 64, BATCH * NHEADS), 128, ATTN_DYN>>>();

    out_mma_kernel<<<dim3(D_MODEL / TN, MTOT / TM), 256, GEMM_DYN>>>(bo, out);
}